// round 5
// baseline (speedup 1.0000x reference)
#include <cuda_runtime.h>
#include <math.h>

#define NSPEC 300
#define NPADI 304
#define NPADJ 320
#define NMEAS 9
#define NLAY  5
#define RROWS 32
#define TI    8
#define NT    38            // 304/8
#define SROW  321           // odd stride -> conflict-free column reads
#define TH_MAIN 512
#define TILEF (TI*NPADJ)    // 2560 floats per tile buffer
#define SMEM_BYTES ((5*RROWS*SROW + 2*TILEF)*4)   // 225,920 B

__device__ float  g_Minv[NLAY][NPADI][NPADJ];
__device__ double g_B[NLAY][NMEAS][NSPEC];
__device__ double g_G[NLAY][NMEAS][NSPEC];

// ---------------- PTX helpers ----------------
__device__ __forceinline__ unsigned long long pk2(float x, float y) {
    unsigned long long r; asm("mov.b64 %0,{%1,%2};" : "=l"(r) : "f"(x), "f"(y)); return r;
}
__device__ __forceinline__ void ffma2(unsigned long long& d, unsigned long long a, unsigned long long b) {
    asm("fma.rn.f32x2 %0, %1, %2, %0;" : "+l"(d) : "l"(a), "l"(b));
}
__device__ __forceinline__ void lds_v2u64(unsigned long long& a, unsigned long long& b, unsigned int addr) {
    asm volatile("ld.shared.v2.u64 {%0,%1},[%2];" : "=l"(a), "=l"(b) : "r"(addr));
}
__device__ __forceinline__ void cp16(unsigned int dst, const void* src) {
    asm volatile("cp.async.cg.shared.global [%0],[%1],16;" :: "r"(dst), "l"(src) : "memory");
}
__device__ __forceinline__ void cpcommit() { asm volatile("cp.async.commit_group;" ::: "memory"); }
template<int N> __device__ __forceinline__ void cpwait() { asm volatile("cp.async.wait_group %0;" :: "n"(N) : "memory"); }

// ============ precompute M^-1 via Woodbury (one block per layer) ============
__global__ void k_pre(const float* __restrict__ A,
                      const float* __restrict__ gamma_tv,
                      const float* __restrict__ alpha) {
    const int l = blockIdx.x, t = threadIdx.x, NTH = blockDim.x;
    const double g = gamma_tv[l], al = alpha[l];
    __shared__ double ct[NSPEC], invlam[NSPEC], vd[NSPEC];
    __shared__ double Ssm[81], Sinv[81];

    for (int m = t; m < NSPEC; m += NTH) {
        double c = cos(6.283185307179586476925287 * (double)m / (double)NSPEC);
        ct[m] = c;
        invlam[m] = 1.0 / (al + 2.0*g - 2.0*g*c);   // eigenvalues of T = al*I + g*DtD
    }
    __syncthreads();
    for (int d = t; d < NSPEC; d += NTH) {          // v[d] = (1/n) sum_m cos(2pi m d/n)/lam_m
        double s = 0.0; int idx = 0;
        for (int m = 0; m < NSPEC; m++) {
            s += ct[idx]*invlam[m];
            idx += d; if (idx >= NSPEC) idx -= NSPEC;
        }
        vd[d] = s / (double)NSPEC;
    }
    __syncthreads();
    // B[k][j] = sum_i A[k][i] * v[(i-j) mod n]
    for (int kj = t; kj < NMEAS*NSPEC; kj += NTH) {
        int k = kj / NSPEC, j = kj - k*NSPEC;
        double s0 = 0, s1 = 0;
        int d = (NSPEC - j) % NSPEC;
        for (int i = 0; i < NSPEC; i += 2) {
            int d1 = d + 1; if (d1 >= NSPEC) d1 -= NSPEC;
            s0 += (double)A[k*NSPEC + i]     * vd[d];
            s1 += (double)A[k*NSPEC + i + 1] * vd[d1];
            d += 2; if (d >= NSPEC) d -= NSPEC;
        }
        g_B[l][k][j] = s0 + s1;
    }
    __syncthreads();
    if (t < 81) {                                    // S = I9 + B A^T
        int k = t / 9, k2 = t - (t/9)*9;
        double s = (k == k2) ? 1.0 : 0.0;
        for (int j = 0; j < NSPEC; j++) s += g_B[l][k][j] * (double)A[k2*NSPEC + j];
        Ssm[t] = s;
    }
    __syncthreads();
    if (t == 0) {                                    // invert 9x9 (Gauss-Jordan, pivoted)
        double M[9][18];
        for (int r = 0; r < 9; r++)
            for (int c = 0; c < 9; c++) { M[r][c] = Ssm[r*9+c]; M[r][c+9] = (r==c) ? 1.0 : 0.0; }
        for (int c = 0; c < 9; c++) {
            int p = c; double best = fabs(M[c][c]);
            for (int r = c+1; r < 9; r++) { double v = fabs(M[r][c]); if (v > best) { best = v; p = r; } }
            if (p != c) for (int q = 0; q < 18; q++) { double tmp = M[c][q]; M[c][q] = M[p][q]; M[p][q] = tmp; }
            double piv = 1.0 / M[c][c];
            for (int q = 0; q < 18; q++) M[c][q] *= piv;
            for (int r = 0; r < 9; r++) if (r != c) {
                double f = M[r][c];
                for (int q = 0; q < 18; q++) M[r][q] -= f * M[c][q];
            }
        }
        for (int r = 0; r < 9; r++) for (int c = 0; c < 9; c++) Sinv[r*9+c] = M[r][c+9];
    }
    __syncthreads();
    for (int kj = t; kj < NMEAS*NSPEC; kj += NTH) {  // G = S^-1 B
        int k = kj / NSPEC, j = kj - (kj/NSPEC)*NSPEC;
        double s = 0;
        for (int k2 = 0; k2 < 9; k2++) s += Sinv[k*9+k2] * g_B[l][k2][j];
        g_G[l][k][j] = s;
    }
    __syncthreads();
    // Minv[i][j] = v[(i-j)%n] - sum_k B[k][i] G[k][j]; pads zeroed
    for (int ij = t; ij < NPADI*NPADJ; ij += NTH) {
        int i = ij / NPADJ, j = ij - i*NPADJ;
        float o = 0.f;
        if (i < NSPEC && j < NSPEC) {
            int d = i - j; if (d < 0) d += NSPEC;
            double s = vd[d];
            for (int k = 0; k < 9; k++) s -= g_B[l][k][i] * g_G[l][k][j];
            o = (float)s;
        }
        g_Minv[l][i][j] = o;
    }
}

// ============ fused 5-layer LADMM, 32 rows per CTA ============
extern __shared__ float smem[];

__global__ __launch_bounds__(TH_MAIN, 1)
void k_main(const float* __restrict__ b, const float* __restrict__ A,
            const float* __restrict__ gamma_tv, const float* __restrict__ lambda_tv,
            const float* __restrict__ alpha, float* __restrict__ out, int batch)
{
    const int t = threadIdx.x, lane = t & 31, w = t >> 5;   // w = column group 0..15
    const int row0 = blockIdx.x * RROWS;

    float* xs   = smem;
    float* res  = smem + RROWS*SROW;
    float* etas = smem + 2*RROWS*SROW;
    float* taus = smem + 3*RROWS*SROW;
    float* bAs  = smem + 4*RROWS*SROW;
    float* tile = smem + 5*RROWS*SROW;                       // 2 x 2560 floats; also init scratch
    const unsigned int tile_sa = (unsigned int)__cvta_generic_to_shared(tile);

    // ---- init: zero x/res buffers (pads must be 0 for i=300..303 reads) ----
    for (int e = t; e < 2*RROWS*SROW; e += TH_MAIN) smem[e] = 0.f;
    for (int e = t; e < NMEAS*NSPEC; e += TH_MAIN) tile[e] = A[e];          // A -> scratch
    if (t < RROWS*NMEAS) {
        int r = t / NMEAS, k = t - r*NMEAS;
        tile[2880 + t] = (row0 + r < batch) ? b[(size_t)(row0+r)*NMEAS + k] : 0.f;
    }
    __syncthreads();
    for (int e = t; e < RROWS*NSPEC; e += TH_MAIN) {         // bA = b@A (once), x=1, duals=0
        int r = e / NSPEC, j = e - r*NSPEC;
        float s = 0.f;
        #pragma unroll
        for (int k = 0; k < NMEAS; k++) s = fmaf(tile[2880 + r*NMEAS + k], tile[k*NSPEC + j], s);
        bAs[r*SROW + j] = s;
        xs [r*SROW + j] = 1.0f;
        etas[r*SROW + j] = 0.f;
        taus[r*SROW + j] = 0.f;
    }
    __syncthreads();

    float* px = xs;      // current x
    float* pr = res;     // residual, then x_new

    for (int l = 0; l < NLAY; l++) {
        const float g = gamma_tv[l], lam = lambda_tv[l], al = alpha[l];
        const float ig = 1.f/g, ial = 1.f/al, th = lam*ig;

        // E1: residual = bA + al*w - tau + g*u - eta
        for (int e = t; e < RROWS*NSPEC; e += TH_MAIN) {
            int r = e / NSPEC, j = e - r*NSPEC;
            int jm = (j == 0) ? (NSPEC-1) : (j-1);
            float xo = px[r*SROW+j], et = etas[r*SROW+j], ta = taus[r*SROW+j];
            float dv = (px[r*SROW+jm] - xo) + et*ig;
            float u  = copysignf(fmaxf(fabsf(dv) - th, 0.f), dv);
            float wv = fmaxf(xo + ta*ial, 0.f);
            pr[r*SROW+j] = bAs[r*SROW+j] + al*wv - ta + g*u - et;
        }
        __syncthreads();

        // matvec: x_new[j] = sum_i res[i] * Minv[i][j]  (FFMA2, cp.async double-buffer)
        unsigned long long acc[10];
        #pragma unroll
        for (int c = 0; c < 10; c++) acc[c] = 0ull;
        const float* gm = &g_Minv[l][0][0];
        for (int idx = t; idx < TILEF/4; idx += TH_MAIN)     // prefetch tile 0
            cp16(tile_sa + idx*16, gm + idx*4);
        cpcommit();
        const int rbase = lane*SROW;
        for (int kt = 0; kt < NT; kt++) {
            cpwait<0>();
            __syncthreads();                                  // tile kt visible
            if (kt + 1 < NT) {
                const float* src = gm + (kt+1)*TILEF;
                unsigned int dst = tile_sa + (unsigned)(((kt+1)&1)*TILEF*4);
                for (int idx = t; idx < TILEF/4; idx += TH_MAIN)
                    cp16(dst + idx*16, src + idx*4);
                cpcommit();
            }
            unsigned int tb = tile_sa + (unsigned)(((kt&1)*TILEF + w*20)*4);
            int i0 = kt*TI;
            #pragma unroll
            for (int ii = 0; ii < TI; ii++) {
                float bc = pr[rbase + i0 + ii];               // 32 banks, conflict-free
                unsigned long long bb = pk2(bc, bc);
                unsigned int ta2 = tb + (unsigned)(ii*NPADJ*4);
                #pragma unroll
                for (int c4 = 0; c4 < 5; c4++) {              // warp-uniform broadcast loads
                    unsigned long long p0, p1;
                    lds_v2u64(p0, p1, ta2 + c4*16);
                    ffma2(acc[2*c4],   p0, bb);
                    ffma2(acc[2*c4+1], p1, bb);
                }
            }
            __syncthreads();                                  // done reading buf kt
        }
        // write x_new over residual (pad cols give exact 0 -> pads stay 0)
        {
            int jb = w*20;
            #pragma unroll
            for (int c = 0; c < 10; c++) {
                float lo, hi;
                asm("mov.b64 {%0,%1},%2;" : "=f"(lo), "=f"(hi) : "l"(acc[c]));
                pr[rbase + jb + 2*c]     = lo;
                pr[rbase + jb + 2*c + 1] = hi;
            }
        }
        __syncthreads();

        // E2: eta += g*(dx_new - u); tau += al*(x_new - w)   (u,w recomputed from old state)
        for (int e = t; e < RROWS*NSPEC; e += TH_MAIN) {
            int r = e / NSPEC, j = e - r*NSPEC;
            int jm = (j == 0) ? (NSPEC-1) : (j-1);
            float xo = px[r*SROW+j], et = etas[r*SROW+j], ta = taus[r*SROW+j];
            float dv = (px[r*SROW+jm] - xo) + et*ig;
            float u  = copysignf(fmaxf(fabsf(dv) - th, 0.f), dv);
            float wv = fmaxf(xo + ta*ial, 0.f);
            float xn = pr[r*SROW+j], xnp = pr[r*SROW+jm];
            etas[r*SROW+j] = et + g*((xnp - xn) - u);
            taus[r*SROW+j] = ta + al*(xn - wv);
        }
        __syncthreads();
        float* tmp = px; px = pr; pr = tmp;                   // swap buffers
    }

    for (int e = t; e < RROWS*NSPEC; e += TH_MAIN) {
        int r = e / NSPEC, j = e - r*NSPEC;
        if (row0 + r < batch)
            out[(size_t)(row0 + r)*NSPEC + j] = px[r*SROW + j];
    }
}

extern "C" void kernel_launch(void* const* d_in, const int* in_sizes, int n_in,
                              void* d_out, int out_size) {
    const float* b         = (const float*)d_in[0];
    // d_in[1] = target: shape-only, values unused by the recurrence
    const float* A         = (const float*)d_in[2];
    const float* gamma_tv  = (const float*)d_in[3];
    const float* lambda_tv = (const float*)d_in[4];
    const float* alpha     = (const float*)d_in[5];
    float* out = (float*)d_out;
    int batch = in_sizes[0] / NMEAS;

    cudaFuncSetAttribute(k_main, cudaFuncAttributeMaxDynamicSharedMemorySize, SMEM_BYTES);
    k_pre <<<NLAY, 320>>>(A, gamma_tv, alpha);
    k_main<<<(batch + RROWS - 1)/RROWS, TH_MAIN, SMEM_BYTES>>>(b, A, gamma_tv, lambda_tv, alpha, out, batch);
    (void)n_in; (void)out_size;
}